// round 16
// baseline (speedup 1.0000x reference)
#include <cuda_runtime.h>
#include <math.h>

#define NMAX   20480
#define KNN    16
#define HDIM   256
#define SAMPLE 8192
#define SUBW   16
#define THTILE 2048                // smem tile for phase A (32KB)
#define THSLICE 2048               // per-y-slice sample range (4 slices)
#define NSLICE 4
#define KTB    512                 // filter candidate tile (16KB smem -> high occupancy)
#define CSPB   48                  // phase-B candidate split: 40x48=1920 blocks ~= 13/SM (residency cap)
#define CAP    1024                // survivor capacity per query

typedef unsigned long long u64;

#define PACK2(d, a) asm("mov.b64 %0, {%1, %2};" : "=l"(d) : "r"(__float_as_uint(a)), "r"(__float_as_uint(a)))
#define PACK2AB(d, a, b) asm("mov.b64 %0, {%1, %2};" : "=l"(d) : "r"(__float_as_uint(a)), "r"(__float_as_uint(b)))
#define FMA2(d, a, b, c) asm("fma.rn.f32x2 %0, %1, %2, %3;" : "=l"(d) : "l"(a), "l"(b), "l"(c))
#define ADD2(d, a, b) asm("add.rn.f32x2 %0, %1, %2;" : "=l"(d) : "l"(a), "l"(b))
#define UNPACK2(lo, hi, in) asm("mov.b64 {%0, %1}, %2;" : "=r"(lo), "=r"(hi) : "l"(in))

// ---------------- scratch (no allocations allowed) ----------------
__device__ float4 g_c4[NMAX];
__device__ float  g_thd[NSLICE * NMAX * KNN];   // per-slice sorted sub-minima top-16
__device__ float  g_thr[NMAX];
__device__ int    g_scnt[NMAX];
__device__ int2   g_surv[(size_t)NMAX * CAP];   // (dist bits, idx)
__device__ int    g_idx[NMAX * KNN];
__device__ int    g_deg[NMAX];
__device__ float  g_srcnorm[NMAX];
__device__ float  g_bufA[NMAX * HDIM];
__device__ float  g_bufB[NMAX * HDIM];
__device__ float  g_bufC[NMAX * HDIM];

__device__ __forceinline__ float* bufptr(int s) {
    return s == 0 ? g_bufA : (s == 1 ? g_bufB : g_bufC);
}

// ---------------- pack centers into float4 (x,y,z,|c|^2), zero degrees/counters --------
__global__ void pack_kernel(const float* __restrict__ centers, int N) {
    int i = blockIdx.x * blockDim.x + threadIdx.x;
    if (i < N) {
        float x = centers[3 * i + 0];
        float y = centers[3 * i + 1];
        float z = centers[3 * i + 2];
        g_c4[i] = make_float4(x, y, z, x * x + y * y + z * z);
        g_deg[i] = 0;
        g_scnt[i] = 0;
    }
}

// ---------------- Phase A: sub-minima top-16 over a sample slice (blockIdx.y) ----------
// Disjoint width-16 sub-blocks: the 16 smallest sub-minima (merged over all slices)
// are 16 distinct candidates all <= t, hence t >= true 16th-NN distance.
__global__ void knn_thresh_kernel(int N) {
    __shared__ float4 sc[THTILE];
    int q = blockIdx.x * blockDim.x + threadIdx.x;
    int y = blockIdx.y;
    int send = min(N, SAMPLE);
    int c0 = y * THSLICE;
    int c1 = min(send, c0 + THSLICE);

    float nx = 0.f, ny = 0.f, nz = 0.f;
    if (q < N) {
        float4 p = g_c4[q];
        nx = -2.f * p.x; ny = -2.f * p.y; nz = -2.f * p.z;
    }
    float bd[KNN];
#pragma unroll
    for (int k = 0; k < KNN; k++) bd[k] = 3.4e38f;

    for (int base = c0; base < c1; base += THTILE) {
        int cnt = min(THTILE, c1 - base);
        __syncthreads();
        for (int t = threadIdx.x; t < cnt; t += blockDim.x) sc[t] = g_c4[base + t];
        __syncthreads();
        if (q < N) {
            int nsub = cnt / SUBW;
            for (int b = 0; b < nsub; b++) {
                float m0 = 3.4e38f, m1 = 3.4e38f;
#pragma unroll
                for (int j = 0; j < SUBW; j++) {
                    float4 v = sc[b * SUBW + j];
                    float d = fmaf(v.x, nx, fmaf(v.y, ny, fmaf(v.z, nz, v.w)));
                    if (j & 1) m1 = fminf(m1, d); else m0 = fminf(m0, d);
                }
                float cd = fminf(m0, m1);
                if (cd < bd[KNN - 1]) {
#pragma unroll
                    for (int k = 0; k < KNN; k++) {
                        float lo = fminf(cd, bd[k]);
                        float hi = fmaxf(cd, bd[k]);
                        bd[k] = lo; cd = hi;
                    }
                }
            }
        }
    }
    if (q < N) {
#pragma unroll
        for (int k = 0; k < KNN; k++) g_thd[((size_t)y * N + q) * KNN + k] = bd[k];
    }
}

// ---------------- merge the NSLICE sorted sub-minima lists -> threshold ----------
__global__ void thr_merge_kernel(int N) {
    int q = blockIdx.x * blockDim.x + threadIdx.x;
    if (q >= N) return;
    const float* L[NSLICE];
#pragma unroll
    for (int l = 0; l < NSLICE; l++) L[l] = &g_thd[((size_t)l * N + q) * KNN];
    int p[NSLICE] = {0, 0, 0, 0};
    float v = 3.4e38f;
#pragma unroll
    for (int k = 0; k < KNN; k++) {
        float best = 3.5e38f;
        int bl = 0;
#pragma unroll
        for (int l = 0; l < NSLICE; l++) {
            float vl = __ldg(&L[l][p[l]]);
            if (vl < best) { best = vl; bl = l; }
        }
        p[bl]++;
        v = best;
    }
    g_thr[q] = v;
}

// ---------------- Phase B: filtered full scan (packed f32x2, QPT=4) ----------------
// Queries partitioned into 4 strides of quarter; survivor test is one sign-mask check:
// d <= th  <=>  d < th' (th' = nextafter(th,+inf))  <=>  sign(d - th') == 1.
// Invalid query lanes get -th' = +inf so d - th' = +inf: sign never set, never fires.
__global__ void knn_filter_kernel(int N) {
    __shared__ u64 sc[KTB][4];          // per candidate: (x,x)(y,y)(z,z)(w,w) = 32B
    int quarter = (N + 3) >> 2;
    int idx = blockIdx.x * blockDim.x + threadIdx.x;
    int q[4];
    u64 nx01, ny01, nz01, nth01, nx23, ny23, nz23, nth23;
    {
        float nx[4], ny[4], nz[4], nth[4];
#pragma unroll
        for (int j = 0; j < 4; j++) {
            q[j] = idx + j * quarter;
            bool vj = (idx < quarter) && (q[j] < N);
            if (vj) {
                float4 p = g_c4[q[j]];
                nx[j] = -2.f * p.x; ny[j] = -2.f * p.y; nz[j] = -2.f * p.z;
                float th = g_thr[q[j]];
                nth[j] = -nextafterf(th, 3.4e38f);   // negated th'
            } else {
                nx[j] = 0.f; ny[j] = 0.f; nz[j] = 0.f;
                nth[j] = __int_as_float(0x7f800000);  // +inf
            }
        }
        PACK2AB(nx01, nx[0], nx[1]); PACK2AB(nx23, nx[2], nx[3]);
        PACK2AB(ny01, ny[0], ny[1]); PACK2AB(ny23, ny[2], ny[3]);
        PACK2AB(nz01, nz[0], nz[1]); PACK2AB(nz23, nz[2], nz[3]);
        PACK2AB(nth01, nth[0], nth[1]); PACK2AB(nth23, nth[2], nth[3]);
    }

    int chunk = (N + CSPB - 1) / CSPB;
    int c0 = blockIdx.y * chunk;
    int c1 = min(N, c0 + chunk);

    for (int base = c0; base < c1; base += KTB) {
        int cnt = min(KTB, c1 - base);
        __syncthreads();
        for (int t = threadIdx.x; t < cnt; t += blockDim.x) {
            float4 v = g_c4[base + t];
            u64 xx, yy, zz, ww;
            PACK2(xx, v.x); PACK2(yy, v.y); PACK2(zz, v.z); PACK2(ww, v.w);
            sc[t][0] = xx; sc[t][1] = yy; sc[t][2] = zz; sc[t][3] = ww;
        }
        __syncthreads();
#pragma unroll 4
        for (int t = 0; t < cnt; t++) {
            ulonglong2 xy = *(const ulonglong2*)&sc[t][0];   // (x,x),(y,y)
            ulonglong2 zw = *(const ulonglong2*)&sc[t][2];   // (z,z),(w,w)
            u64 d01, d23, nd01, nd23;
            FMA2(d01, xy.x, nx01, zw.y);
            FMA2(d23, xy.x, nx23, zw.y);
            FMA2(d01, xy.y, ny01, d01);
            FMA2(d23, xy.y, ny23, d23);
            FMA2(d01, zw.x, nz01, d01);
            FMA2(d23, zw.x, nz23, d23);
            ADD2(nd01, d01, nth01);
            ADD2(nd23, d23, nth23);
            if ((nd01 | nd23) & 0x8000000080000000ull) {
                unsigned v01l, v01h, v23l, v23h;
                UNPACK2(v01l, v01h, d01);
                UNPACK2(v23l, v23h, d23);
                if (nd01 & 0x80000000ull) {
                    int s = atomicAdd(&g_scnt[q[0]], 1);
                    if (s < CAP) g_surv[(size_t)q[0] * CAP + s] = make_int2((int)v01l, base + t);
                }
                if (nd01 & 0x8000000000000000ull) {
                    int s = atomicAdd(&g_scnt[q[1]], 1);
                    if (s < CAP) g_surv[(size_t)q[1] * CAP + s] = make_int2((int)v01h, base + t);
                }
                if (nd23 & 0x80000000ull) {
                    int s = atomicAdd(&g_scnt[q[2]], 1);
                    if (s < CAP) g_surv[(size_t)q[2] * CAP + s] = make_int2((int)v23l, base + t);
                }
                if (nd23 & 0x8000000000000000ull) {
                    int s = atomicAdd(&g_scnt[q[3]], 1);
                    if (s < CAP) g_surv[(size_t)q[3] * CAP + s] = make_int2((int)v23h, base + t);
                }
            }
        }
    }
}

// ---------------- Phase C: exact top-16, deterministic (d, idx) tie-break ---------------
__global__ void knn_select_kernel(int N) {
    __shared__ float sd[32][4][KNN];
    __shared__ int   si[32][4][KNN];
    int tid = threadIdx.x;
    int sub = tid & 3;
    int qi  = tid >> 2;                 // 0..31
    int q = blockIdx.x * 32 + qi;
    bool valid = (q < N);

    float bd[KNN];
    int   bi[KNN];
#pragma unroll
    for (int k = 0; k < KNN; k++) { bd[k] = 3.4e38f; bi[k] = 0x7fffffff; }

    if (valid) {
        int cnt = min(g_scnt[q], CAP);
        const int2* sv = &g_surv[(size_t)q * CAP];
        for (int s = sub; s < cnt; s += 4) {
            int2 e = __ldg(&sv[s]);
            float cd = __int_as_float(e.x);
            if (cd <= bd[KNN - 1]) {
                int ci = e.y;
#pragma unroll
                for (int k = 0; k < KNN; k++) {
                    bool lt = (cd < bd[k]) || (cd == bd[k] && ci < bi[k]);
                    float lo = fminf(cd, bd[k]);
                    float hi = fmaxf(cd, bd[k]);
                    int ni = lt ? ci : bi[k];
                    ci = lt ? bi[k] : ci;
                    bd[k] = lo; bi[k] = ni; cd = hi;
                }
            }
        }
    }
#pragma unroll
    for (int k = 0; k < KNN; k++) {
        sd[qi][sub][k] = bd[k];
        si[qi][sub][k] = bi[k];
    }
    __syncthreads();

    if (valid && sub == 0) {
        int p[4] = {0, 0, 0, 0};
#pragma unroll
        for (int k = 0; k < KNN; k++) {
            float best = 3.5e38f;
            int bidx = 0x7fffffff;
            int bl = 0;
#pragma unroll
            for (int l = 0; l < 4; l++) {
                float v = (p[l] < KNN) ? sd[qi][l][p[l]] : 3.5e38f;
                int ix = (p[l] < KNN) ? si[qi][l][p[l]] : 0x7fffffff;
                if (v < best || (v == best && ix < bidx)) { best = v; bidx = ix; bl = l; }
            }
            p[bl]++;
            g_idx[q * KNN + k] = bidx;
            atomicAdd(&g_deg[bidx], 1);
        }
    }
}

// ---------------- src_norm = rsqrt(max(out_deg,1)) ----------------
__global__ void norm_kernel(int N) {
    int i = blockIdx.x * blockDim.x + threadIdx.x;
    if (i < N) {
        float d = (float)g_deg[i];
        g_srcnorm[i] = rsqrtf(fmaxf(d, 1.f));
    }
}

// ---------------- neighbor aggregation: agg[i] = 0.25 * sum_k srcnorm[j]*h[j] ----------
__global__ void agg_kernel(const float* __restrict__ xin, int srcSel, int dstSel,
                           int F, int N) {
    const float* src = (srcSel < 0) ? xin : bufptr(srcSel);
    float* dst = bufptr(dstSel);
    int tpr = F >> 2;
    int rpb = blockDim.x / tpr;
    int r = threadIdx.x / tpr;
    int c = threadIdx.x % tpr;
    int node = blockIdx.x * rpb + r;
    if (node >= N) return;
    const float4* s4 = (const float4*)src;
    float4 acc = make_float4(0.f, 0.f, 0.f, 0.f);
    const int* ip = &g_idx[node * KNN];
#pragma unroll
    for (int k = 0; k < KNN; k++) {
        int j = __ldg(&ip[k]);
        float s = __ldg(&g_srcnorm[j]);
        float4 v = s4[j * tpr + c];
        acc.x = fmaf(s, v.x, acc.x);
        acc.y = fmaf(s, v.y, acc.y);
        acc.z = fmaf(s, v.z, acc.z);
        acc.w = fmaf(s, v.w, acc.w);
    }
    const float dn = 0.25f;
    ((float4*)dst)[node * tpr + c] =
        make_float4(acc.x * dn, acc.y * dn, acc.z * dn, acc.w * dn);
}

// ---------------- fp32 tiled GEMM (packed f32x2 FFMA) + bias + relu --------------------
// BM=128, BN=128, BK=16, 256 threads, 8x8 micro-tile as 8x4 f32x2 pairs  (R8/R13-proven)
__global__ void gemm_kernel(int srcSel, const float* __restrict__ W,
                            const float* __restrict__ bias, int dstSel,
                            int M, int Kd) {
    const float* A = bufptr(srcSel);
    float* C = bufptr(dstSel);
    __shared__ float As[16][132];
    __shared__ float Bs[16][128];
    int tid = threadIdx.x;
    int tx = tid & 15;
    int ty = tid >> 4;
    int bm0 = blockIdx.x * 128;
    int bn0 = blockIdx.y * 128;

    u64 acc2[8][4];
#pragma unroll
    for (int i = 0; i < 8; i++)
#pragma unroll
        for (int j = 0; j < 4; j++) acc2[i][j] = 0ull;

    int ktiles = Kd >> 4;
    for (int kt = 0; kt < ktiles; kt++) {
#pragma unroll
        for (int l = 0; l < 2; l++) {
            int lin = tid + l * 256;
            int arow = lin >> 2;
            int kq = (lin & 3) << 2;
            int grow = bm0 + arow;
            float4 v = make_float4(0.f, 0.f, 0.f, 0.f);
            if (grow < M) v = *(const float4*)&A[grow * Kd + kt * 16 + kq];
            As[kq + 0][arow] = v.x;
            As[kq + 1][arow] = v.y;
            As[kq + 2][arow] = v.z;
            As[kq + 3][arow] = v.w;
        }
#pragma unroll
        for (int l = 0; l < 2; l++) {
            int lin = tid + l * 256;
            int brow = lin >> 5;
            int bc = (lin & 31) << 2;
            float4 v = *(const float4*)&W[(kt * 16 + brow) * HDIM + bn0 + bc];
            *(float4*)&Bs[brow][bc] = v;
        }
        __syncthreads();
#pragma unroll
        for (int kk = 0; kk < 16; kk++) {
            float4 a0 = *(const float4*)&As[kk][ty * 8];
            float4 a1 = *(const float4*)&As[kk][ty * 8 + 4];
            ulonglong2 bp01 = *(const ulonglong2*)&Bs[kk][tx * 8];
            ulonglong2 bp23 = *(const ulonglong2*)&Bs[kk][tx * 8 + 4];
            u64 bp[4] = {bp01.x, bp01.y, bp23.x, bp23.y};
            float a[8] = {a0.x, a0.y, a0.z, a0.w, a1.x, a1.y, a1.z, a1.w};
#pragma unroll
            for (int i = 0; i < 8; i++) {
                u64 aa;
                PACK2(aa, a[i]);
#pragma unroll
                for (int j = 0; j < 4; j++)
                    FMA2(acc2[i][j], aa, bp[j], acc2[i][j]);
            }
        }
        __syncthreads();
    }

    float bb[8];
#pragma unroll
    for (int j = 0; j < 8; j++) bb[j] = __ldg(&bias[bn0 + tx * 8 + j]);
#pragma unroll
    for (int i = 0; i < 8; i++) {
        int row = bm0 + ty * 8 + i;
        if (row < M) {
            float o[8];
#pragma unroll
            for (int j = 0; j < 4; j++) {
                unsigned int lo, hi;
                UNPACK2(lo, hi, acc2[i][j]);
                o[2 * j + 0] = fmaxf(__uint_as_float(lo) + bb[2 * j + 0], 0.f);
                o[2 * j + 1] = fmaxf(__uint_as_float(hi) + bb[2 * j + 1], 0.f);
            }
            *(float4*)&C[row * HDIM + bn0 + tx * 8 + 0] = make_float4(o[0], o[1], o[2], o[3]);
            *(float4*)&C[row * HDIM + bn0 + tx * 8 + 4] = make_float4(o[4], o[5], o[6], o[7]);
        }
    }
}

// ---------------- final: sigmoid(h @ Wf + bf), one warp per row ----------------
__global__ void final_kernel(int srcSel, const float* __restrict__ Wf,
                             const float* __restrict__ bf,
                             float* __restrict__ out, int N) {
    __shared__ float sw[HDIM];
    const float* h = bufptr(srcSel);
    for (int i = threadIdx.x; i < HDIM; i += blockDim.x) sw[i] = Wf[i];
    __syncthreads();
    int warp = threadIdx.x >> 5;
    int lane = threadIdx.x & 31;
    int row = blockIdx.x * 8 + warp;
    if (row >= N) return;
    const float4* h4 = (const float4*)&h[row * HDIM];
    float4 v0 = h4[lane * 2 + 0];
    float4 v1 = h4[lane * 2 + 1];
    float4 w0 = *(const float4*)&sw[lane * 8 + 0];
    float4 w1 = *(const float4*)&sw[lane * 8 + 4];
    float s = v0.x * w0.x + v0.y * w0.y + v0.z * w0.z + v0.w * w0.w
            + v1.x * w1.x + v1.y * w1.y + v1.z * w1.z + v1.w * w1.w;
#pragma unroll
    for (int o = 16; o > 0; o >>= 1) s += __shfl_xor_sync(0xffffffffu, s, o);
    if (lane == 0) {
        float z = s + bf[0];
        out[row] = 1.f / (1.f + expf(-z));
    }
}

// ---------------- launch ----------------
extern "C" void kernel_launch(void* const* d_in, const int* in_sizes, int n_in,
                              void* d_out, int out_size) {
    const float* x       = (const float*)d_in[0];
    const float* centers = (const float*)d_in[1];
    const float* W0      = (const float*)d_in[2];
    const float* b0      = (const float*)d_in[3];
    const float* W1      = (const float*)d_in[4];
    const float* b1      = (const float*)d_in[5];
    const float* W2      = (const float*)d_in[6];
    const float* b2      = (const float*)d_in[7];
    const float* Wf      = (const float*)d_in[8];
    const float* bf      = (const float*)d_in[9];
    float* out = (float*)d_out;

    int N = in_sizes[1] / 3;           // 20000
    int D = in_sizes[0] / N;           // 128

    pack_kernel<<<(N + 255) / 256, 256>>>(centers, N);
    {
        dim3 tg((N + 127) / 128, NSLICE);
        knn_thresh_kernel<<<tg, 128>>>(N);
    }
    thr_merge_kernel<<<(N + 255) / 256, 256>>>(N);
    {
        int quarter = (N + 3) / 4;
        dim3 kg((quarter + 127) / 128, CSPB);
        knn_filter_kernel<<<kg, 128>>>(N);
    }
    knn_select_kernel<<<(N + 31) / 32, 128>>>(N);
    norm_kernel<<<(N + 255) / 256, 256>>>(N);

    dim3 gg((N + 127) / 128, HDIM / 128);

    {
        int tpr = D / 4, rpb = 256 / tpr;
        agg_kernel<<<(N + rpb - 1) / rpb, 256>>>(x, -1, 0, D, N);
    }
    gemm_kernel<<<gg, 256>>>(0, W0, b0, 1, N, D);

    {
        int tpr = HDIM / 4, rpb = 256 / tpr;
        agg_kernel<<<(N + rpb - 1) / rpb, 256>>>(nullptr, 1, 0, HDIM, N);
    }
    gemm_kernel<<<gg, 256>>>(0, W1, b1, 2, N, HDIM);

    {
        int tpr = HDIM / 4, rpb = 256 / tpr;
        agg_kernel<<<(N + rpb - 1) / rpb, 256>>>(nullptr, 2, 0, HDIM, N);
    }
    gemm_kernel<<<gg, 256>>>(0, W2, b2, 1, N, HDIM);

    final_kernel<<<(N + 7) / 8, 256>>>(1, Wf, bf, out, N);
}

// round 17
// speedup vs baseline: 1.6010x; 1.6010x over previous
#include <cuda_runtime.h>
#include <math.h>

#define NMAX   20480
#define KNN    16
#define HDIM   256
#define SAMPLE 8192
#define SUBW   16
#define THTILE 2048                // smem tile for phase A (32KB)
#define THSLICE 2048               // per-y-slice sample range (4 slices)
#define NSLICE 4
#define KTB    512                 // filter candidate tile (16KB smem)
#define CSPB   32                  // phase-B candidate split (R13-proven)
#define CAP    1024                // survivor capacity per query

typedef unsigned long long u64;

#define PACK2(d, a) asm("mov.b64 %0, {%1, %2};" : "=l"(d) : "r"(__float_as_uint(a)), "r"(__float_as_uint(a)))
#define PACK2AB(d, a, b) asm("mov.b64 %0, {%1, %2};" : "=l"(d) : "r"(__float_as_uint(a)), "r"(__float_as_uint(b)))
#define FMA2(d, a, b, c) asm("fma.rn.f32x2 %0, %1, %2, %3;" : "=l"(d) : "l"(a), "l"(b), "l"(c))
#define ADD2(d, a, b) asm("add.rn.f32x2 %0, %1, %2;" : "=l"(d) : "l"(a), "l"(b))
#define UNPACK2(lo, hi, in) asm("mov.b64 {%0, %1}, %2;" : "=r"(lo), "=r"(hi) : "l"(in))

// ---------------- scratch (no allocations allowed) ----------------
__device__ float4 g_c4[NMAX];
__device__ float  g_thd[NSLICE * NMAX * KNN];   // per-slice sorted sub-minima top-16
__device__ float  g_thr[NMAX];
__device__ int    g_scnt[NMAX];
__device__ int2   g_surv[(size_t)NMAX * CAP];   // (dist bits, idx)
__device__ int    g_idx[NMAX * KNN];
__device__ int    g_deg[NMAX];
__device__ float  g_srcnorm[NMAX];
__device__ float  g_bufA[NMAX * HDIM];
__device__ float  g_bufB[NMAX * HDIM];
__device__ float  g_bufC[NMAX * HDIM];

__device__ __forceinline__ float* bufptr(int s) {
    return s == 0 ? g_bufA : (s == 1 ? g_bufB : g_bufC);
}

// ---------------- pack centers into float4 (x,y,z,|c|^2), zero degrees/counters --------
__global__ void pack_kernel(const float* __restrict__ centers, int N) {
    int i = blockIdx.x * blockDim.x + threadIdx.x;
    if (i < N) {
        float x = centers[3 * i + 0];
        float y = centers[3 * i + 1];
        float z = centers[3 * i + 2];
        g_c4[i] = make_float4(x, y, z, x * x + y * y + z * z);
        g_deg[i] = 0;
        g_scnt[i] = 0;
    }
}

// ---------------- Phase A: sub-minima top-16 over a sample slice (blockIdx.y) ----------
// Disjoint width-16 sub-blocks: the 16 smallest sub-minima (merged over all slices)
// are 16 distinct candidates all <= t, hence t >= true 16th-NN distance.
__global__ void knn_thresh_kernel(int N) {
    __shared__ float4 sc[THTILE];
    int q = blockIdx.x * blockDim.x + threadIdx.x;
    int y = blockIdx.y;
    int send = min(N, SAMPLE);
    int c0 = y * THSLICE;
    int c1 = min(send, c0 + THSLICE);

    float nx = 0.f, ny = 0.f, nz = 0.f;
    if (q < N) {
        float4 p = g_c4[q];
        nx = -2.f * p.x; ny = -2.f * p.y; nz = -2.f * p.z;
    }
    float bd[KNN];
#pragma unroll
    for (int k = 0; k < KNN; k++) bd[k] = 3.4e38f;

    for (int base = c0; base < c1; base += THTILE) {
        int cnt = min(THTILE, c1 - base);
        __syncthreads();
        for (int t = threadIdx.x; t < cnt; t += blockDim.x) sc[t] = g_c4[base + t];
        __syncthreads();
        if (q < N) {
            int nsub = cnt / SUBW;
            for (int b = 0; b < nsub; b++) {
                float m0 = 3.4e38f, m1 = 3.4e38f;
#pragma unroll
                for (int j = 0; j < SUBW; j++) {
                    float4 v = sc[b * SUBW + j];
                    float d = fmaf(v.x, nx, fmaf(v.y, ny, fmaf(v.z, nz, v.w)));
                    if (j & 1) m1 = fminf(m1, d); else m0 = fminf(m0, d);
                }
                float cd = fminf(m0, m1);
                if (cd < bd[KNN - 1]) {
#pragma unroll
                    for (int k = 0; k < KNN; k++) {
                        float lo = fminf(cd, bd[k]);
                        float hi = fmaxf(cd, bd[k]);
                        bd[k] = lo; cd = hi;
                    }
                }
            }
        }
    }
    if (q < N) {
#pragma unroll
        for (int k = 0; k < KNN; k++) g_thd[((size_t)y * N + q) * KNN + k] = bd[k];
    }
}

// ---------------- merge the NSLICE sorted sub-minima lists -> threshold ----------
__global__ void thr_merge_kernel(int N) {
    int q = blockIdx.x * blockDim.x + threadIdx.x;
    if (q >= N) return;
    const float* L[NSLICE];
#pragma unroll
    for (int l = 0; l < NSLICE; l++) L[l] = &g_thd[((size_t)l * N + q) * KNN];
    int p[NSLICE] = {0, 0, 0, 0};
    float v = 3.4e38f;
#pragma unroll
    for (int k = 0; k < KNN; k++) {
        float best = 3.5e38f;
        int bl = 0;
#pragma unroll
        for (int l = 0; l < NSLICE; l++) {
            float vl = __ldg(&L[l][p[l]]);
            if (vl < best) { best = vl; bl = l; }
        }
        p[bl]++;
        v = best;
    }
    g_thr[q] = v;
}

// ---------------- Phase B: filtered full scan (packed f32x2, QPT=4)  (R13-proven) -------
// Survivor test: d <= th  <=>  d < th' (th' = nextafter(th,+inf))  <=>  sign(d - th')==1.
// Invalid query lanes get -th' = +inf so d - th' = +inf: sign never set, never fires.
__global__ void knn_filter_kernel(int N) {
    __shared__ u64 sc[KTB][4];          // per candidate: (x,x)(y,y)(z,z)(w,w) = 32B
    int quarter = (N + 3) >> 2;
    int idx = blockIdx.x * blockDim.x + threadIdx.x;
    int q[4];
    u64 nx01, ny01, nz01, nth01, nx23, ny23, nz23, nth23;
    {
        float nx[4], ny[4], nz[4], nth[4];
#pragma unroll
        for (int j = 0; j < 4; j++) {
            q[j] = idx + j * quarter;
            bool vj = (idx < quarter) && (q[j] < N);
            if (vj) {
                float4 p = g_c4[q[j]];
                nx[j] = -2.f * p.x; ny[j] = -2.f * p.y; nz[j] = -2.f * p.z;
                float th = g_thr[q[j]];
                nth[j] = -nextafterf(th, 3.4e38f);   // negated th'
            } else {
                nx[j] = 0.f; ny[j] = 0.f; nz[j] = 0.f;
                nth[j] = __int_as_float(0x7f800000);  // +inf
            }
        }
        PACK2AB(nx01, nx[0], nx[1]); PACK2AB(nx23, nx[2], nx[3]);
        PACK2AB(ny01, ny[0], ny[1]); PACK2AB(ny23, ny[2], ny[3]);
        PACK2AB(nz01, nz[0], nz[1]); PACK2AB(nz23, nz[2], nz[3]);
        PACK2AB(nth01, nth[0], nth[1]); PACK2AB(nth23, nth[2], nth[3]);
    }

    int chunk = (N + CSPB - 1) / CSPB;
    int c0 = blockIdx.y * chunk;
    int c1 = min(N, c0 + chunk);

    for (int base = c0; base < c1; base += KTB) {
        int cnt = min(KTB, c1 - base);
        __syncthreads();
        for (int t = threadIdx.x; t < cnt; t += blockDim.x) {
            float4 v = g_c4[base + t];
            u64 xx, yy, zz, ww;
            PACK2(xx, v.x); PACK2(yy, v.y); PACK2(zz, v.z); PACK2(ww, v.w);
            sc[t][0] = xx; sc[t][1] = yy; sc[t][2] = zz; sc[t][3] = ww;
        }
        __syncthreads();
#pragma unroll 4
        for (int t = 0; t < cnt; t++) {
            ulonglong2 xy = *(const ulonglong2*)&sc[t][0];   // (x,x),(y,y)
            ulonglong2 zw = *(const ulonglong2*)&sc[t][2];   // (z,z),(w,w)
            u64 d01, d23, nd01, nd23;
            FMA2(d01, xy.x, nx01, zw.y);
            FMA2(d23, xy.x, nx23, zw.y);
            FMA2(d01, xy.y, ny01, d01);
            FMA2(d23, xy.y, ny23, d23);
            FMA2(d01, zw.x, nz01, d01);
            FMA2(d23, zw.x, nz23, d23);
            ADD2(nd01, d01, nth01);
            ADD2(nd23, d23, nth23);
            if ((nd01 | nd23) & 0x8000000080000000ull) {
                unsigned v01l, v01h, v23l, v23h;
                UNPACK2(v01l, v01h, d01);
                UNPACK2(v23l, v23h, d23);
                if (nd01 & 0x80000000ull) {
                    int s = atomicAdd(&g_scnt[q[0]], 1);
                    if (s < CAP) g_surv[(size_t)q[0] * CAP + s] = make_int2((int)v01l, base + t);
                }
                if (nd01 & 0x8000000000000000ull) {
                    int s = atomicAdd(&g_scnt[q[1]], 1);
                    if (s < CAP) g_surv[(size_t)q[1] * CAP + s] = make_int2((int)v01h, base + t);
                }
                if (nd23 & 0x80000000ull) {
                    int s = atomicAdd(&g_scnt[q[2]], 1);
                    if (s < CAP) g_surv[(size_t)q[2] * CAP + s] = make_int2((int)v23l, base + t);
                }
                if (nd23 & 0x8000000000000000ull) {
                    int s = atomicAdd(&g_scnt[q[3]], 1);
                    if (s < CAP) g_surv[(size_t)q[3] * CAP + s] = make_int2((int)v23h, base + t);
                }
            }
        }
    }
}

// ---------------- Phase C: exact top-16, deterministic (d, idx) tie-break ---------------
__global__ void knn_select_kernel(int N) {
    __shared__ float sd[32][4][KNN];
    __shared__ int   si[32][4][KNN];
    int tid = threadIdx.x;
    int sub = tid & 3;
    int qi  = tid >> 2;                 // 0..31
    int q = blockIdx.x * 32 + qi;
    bool valid = (q < N);

    float bd[KNN];
    int   bi[KNN];
#pragma unroll
    for (int k = 0; k < KNN; k++) { bd[k] = 3.4e38f; bi[k] = 0x7fffffff; }

    if (valid) {
        int cnt = min(g_scnt[q], CAP);
        const int2* sv = &g_surv[(size_t)q * CAP];
        for (int s = sub; s < cnt; s += 4) {
            int2 e = __ldg(&sv[s]);
            float cd = __int_as_float(e.x);
            if (cd <= bd[KNN - 1]) {
                int ci = e.y;
#pragma unroll
                for (int k = 0; k < KNN; k++) {
                    bool lt = (cd < bd[k]) || (cd == bd[k] && ci < bi[k]);
                    float lo = fminf(cd, bd[k]);
                    float hi = fmaxf(cd, bd[k]);
                    int ni = lt ? ci : bi[k];
                    ci = lt ? bi[k] : ci;
                    bd[k] = lo; bi[k] = ni; cd = hi;
                }
            }
        }
    }
#pragma unroll
    for (int k = 0; k < KNN; k++) {
        sd[qi][sub][k] = bd[k];
        si[qi][sub][k] = bi[k];
    }
    __syncthreads();

    if (valid && sub == 0) {
        int p[4] = {0, 0, 0, 0};
#pragma unroll
        for (int k = 0; k < KNN; k++) {
            float best = 3.5e38f;
            int bidx = 0x7fffffff;
            int bl = 0;
#pragma unroll
            for (int l = 0; l < 4; l++) {
                float v = (p[l] < KNN) ? sd[qi][l][p[l]] : 3.5e38f;
                int ix = (p[l] < KNN) ? si[qi][l][p[l]] : 0x7fffffff;
                if (v < best || (v == best && ix < bidx)) { best = v; bidx = ix; bl = l; }
            }
            p[bl]++;
            g_idx[q * KNN + k] = bidx;
            atomicAdd(&g_deg[bidx], 1);
        }
    }
}

// ---------------- src_norm = rsqrt(max(out_deg,1)) ----------------
__global__ void norm_kernel(int N) {
    int i = blockIdx.x * blockDim.x + threadIdx.x;
    if (i < N) {
        float d = (float)g_deg[i];
        g_srcnorm[i] = rsqrtf(fmaxf(d, 1.f));
    }
}

// ---------------- neighbor aggregation: agg[i] = 0.25 * sum_k srcnorm[j]*h[j] ----------
__global__ void agg_kernel(const float* __restrict__ xin, int srcSel, int dstSel,
                           int F, int N) {
    const float* src = (srcSel < 0) ? xin : bufptr(srcSel);
    float* dst = bufptr(dstSel);
    int tpr = F >> 2;
    int rpb = blockDim.x / tpr;
    int r = threadIdx.x / tpr;
    int c = threadIdx.x % tpr;
    int node = blockIdx.x * rpb + r;
    if (node >= N) return;
    const float4* s4 = (const float4*)src;
    float4 acc = make_float4(0.f, 0.f, 0.f, 0.f);
    const int* ip = &g_idx[node * KNN];
#pragma unroll
    for (int k = 0; k < KNN; k++) {
        int j = __ldg(&ip[k]);
        float s = __ldg(&g_srcnorm[j]);
        float4 v = s4[j * tpr + c];
        acc.x = fmaf(s, v.x, acc.x);
        acc.y = fmaf(s, v.y, acc.y);
        acc.z = fmaf(s, v.z, acc.z);
        acc.w = fmaf(s, v.w, acc.w);
    }
    const float dn = 0.25f;
    ((float4*)dst)[node * tpr + c] =
        make_float4(acc.x * dn, acc.y * dn, acc.z * dn, acc.w * dn);
}

// ---------------- fp32 tiled GEMM (packed f32x2 FFMA) + bias + relu --------------------
// BM=128, BN=128, BK=32, 256 threads, 8x8 micro-tile as 8x4 f32x2 pairs.
// Same inner loop as the R8/R13-proven version; BK doubled to halve barrier count.
__global__ void gemm_kernel(int srcSel, const float* __restrict__ W,
                            const float* __restrict__ bias, int dstSel,
                            int M, int Kd) {
    const float* A = bufptr(srcSel);
    float* C = bufptr(dstSel);
    __shared__ float As[32][132];
    __shared__ float Bs[32][128];
    int tid = threadIdx.x;
    int tx = tid & 15;
    int ty = tid >> 4;
    int bm0 = blockIdx.x * 128;
    int bn0 = blockIdx.y * 128;

    u64 acc2[8][4];
#pragma unroll
    for (int i = 0; i < 8; i++)
#pragma unroll
        for (int j = 0; j < 4; j++) acc2[i][j] = 0ull;

    int ktiles = Kd >> 5;
    for (int kt = 0; kt < ktiles; kt++) {
        // load A tile: 128 rows x 32 k = 1024 float4, 4 per thread, transposed store
#pragma unroll
        for (int l = 0; l < 4; l++) {
            int lin = tid + l * 256;
            int arow = lin >> 3;              // 0..127
            int kq = (lin & 7) << 2;          // 0,4,...,28
            int grow = bm0 + arow;
            float4 v = make_float4(0.f, 0.f, 0.f, 0.f);
            if (grow < M) v = *(const float4*)&A[grow * Kd + kt * 32 + kq];
            As[kq + 0][arow] = v.x;
            As[kq + 1][arow] = v.y;
            As[kq + 2][arow] = v.z;
            As[kq + 3][arow] = v.w;
        }
        // load B tile: 32 k x 128 cols = 1024 float4, 4 per thread
#pragma unroll
        for (int l = 0; l < 4; l++) {
            int lin = tid + l * 256;
            int brow = lin >> 5;              // 0..31
            int bc = (lin & 31) << 2;         // 0..124
            float4 v = *(const float4*)&W[(kt * 32 + brow) * HDIM + bn0 + bc];
            *(float4*)&Bs[brow][bc] = v;
        }
        __syncthreads();
#pragma unroll
        for (int kk = 0; kk < 32; kk++) {
            float4 a0 = *(const float4*)&As[kk][ty * 8];
            float4 a1 = *(const float4*)&As[kk][ty * 8 + 4];
            ulonglong2 bp01 = *(const ulonglong2*)&Bs[kk][tx * 8];
            ulonglong2 bp23 = *(const ulonglong2*)&Bs[kk][tx * 8 + 4];
            u64 bp[4] = {bp01.x, bp01.y, bp23.x, bp23.y};
            float a[8] = {a0.x, a0.y, a0.z, a0.w, a1.x, a1.y, a1.z, a1.w};
#pragma unroll
            for (int i = 0; i < 8; i++) {
                u64 aa;
                PACK2(aa, a[i]);
#pragma unroll
                for (int j = 0; j < 4; j++)
                    FMA2(acc2[i][j], aa, bp[j], acc2[i][j]);
            }
        }
        __syncthreads();
    }

    float bb[8];
#pragma unroll
    for (int j = 0; j < 8; j++) bb[j] = __ldg(&bias[bn0 + tx * 8 + j]);
#pragma unroll
    for (int i = 0; i < 8; i++) {
        int row = bm0 + ty * 8 + i;
        if (row < M) {
            float o[8];
#pragma unroll
            for (int j = 0; j < 4; j++) {
                unsigned int lo, hi;
                UNPACK2(lo, hi, acc2[i][j]);
                o[2 * j + 0] = fmaxf(__uint_as_float(lo) + bb[2 * j + 0], 0.f);
                o[2 * j + 1] = fmaxf(__uint_as_float(hi) + bb[2 * j + 1], 0.f);
            }
            *(float4*)&C[row * HDIM + bn0 + tx * 8 + 0] = make_float4(o[0], o[1], o[2], o[3]);
            *(float4*)&C[row * HDIM + bn0 + tx * 8 + 4] = make_float4(o[4], o[5], o[6], o[7]);
        }
    }
}

// ---------------- final: sigmoid(h @ Wf + bf), one warp per row ----------------
__global__ void final_kernel(int srcSel, const float* __restrict__ Wf,
                             const float* __restrict__ bf,
                             float* __restrict__ out, int N) {
    __shared__ float sw[HDIM];
    const float* h = bufptr(srcSel);
    for (int i = threadIdx.x; i < HDIM; i += blockDim.x) sw[i] = Wf[i];
    __syncthreads();
    int warp = threadIdx.x >> 5;
    int lane = threadIdx.x & 31;
    int row = blockIdx.x * 8 + warp;
    if (row >= N) return;
    const float4* h4 = (const float4*)&h[row * HDIM];
    float4 v0 = h4[lane * 2 + 0];
    float4 v1 = h4[lane * 2 + 1];
    float4 w0 = *(const float4*)&sw[lane * 8 + 0];
    float4 w1 = *(const float4*)&sw[lane * 8 + 4];
    float s = v0.x * w0.x + v0.y * w0.y + v0.z * w0.z + v0.w * w0.w
            + v1.x * w1.x + v1.y * w1.y + v1.z * w1.z + v1.w * w1.w;
#pragma unroll
    for (int o = 16; o > 0; o >>= 1) s += __shfl_xor_sync(0xffffffffu, s, o);
    if (lane == 0) {
        float z = s + bf[0];
        out[row] = 1.f / (1.f + expf(-z));
    }
}

// ---------------- launch ----------------
extern "C" void kernel_launch(void* const* d_in, const int* in_sizes, int n_in,
                              void* d_out, int out_size) {
    const float* x       = (const float*)d_in[0];
    const float* centers = (const float*)d_in[1];
    const float* W0      = (const float*)d_in[2];
    const float* b0      = (const float*)d_in[3];
    const float* W1      = (const float*)d_in[4];
    const float* b1      = (const float*)d_in[5];
    const float* W2      = (const float*)d_in[6];
    const float* b2      = (const float*)d_in[7];
    const float* Wf      = (const float*)d_in[8];
    const float* bf      = (const float*)d_in[9];
    float* out = (float*)d_out;

    int N = in_sizes[1] / 3;           // 20000
    int D = in_sizes[0] / N;           // 128

    pack_kernel<<<(N + 255) / 256, 256>>>(centers, N);
    {
        dim3 tg((N + 127) / 128, NSLICE);
        knn_thresh_kernel<<<tg, 128>>>(N);
    }
    thr_merge_kernel<<<(N + 255) / 256, 256>>>(N);
    {
        int quarter = (N + 3) / 4;
        dim3 kg((quarter + 127) / 128, CSPB);
        knn_filter_kernel<<<kg, 128>>>(N);
    }
    knn_select_kernel<<<(N + 31) / 32, 128>>>(N);
    norm_kernel<<<(N + 255) / 256, 256>>>(N);

    dim3 gg((N + 127) / 128, HDIM / 128);

    {
        int tpr = D / 4, rpb = 256 / tpr;
        agg_kernel<<<(N + rpb - 1) / rpb, 256>>>(x, -1, 0, D, N);
    }
    gemm_kernel<<<gg, 256>>>(0, W0, b0, 1, N, D);

    {
        int tpr = HDIM / 4, rpb = 256 / tpr;
        agg_kernel<<<(N + rpb - 1) / rpb, 256>>>(nullptr, 1, 0, HDIM, N);
    }
    gemm_kernel<<<gg, 256>>>(0, W1, b1, 2, N, HDIM);

    {
        int tpr = HDIM / 4, rpb = 256 / tpr;
        agg_kernel<<<(N + rpb - 1) / rpb, 256>>>(nullptr, 2, 0, HDIM, N);
    }
    gemm_kernel<<<gg, 256>>>(0, W2, b2, 1, N, HDIM);

    final_kernel<<<(N + 7) / 8, 256>>>(1, Wf, bf, out, N);
}